// round 12
// baseline (speedup 1.0000x reference)
#include <cuda_runtime.h>
#include <cstdint>

// ---------------- problem constants ----------------
#define B      128
#define D      768
#define POOL   100
#define LG     6
#define LE     6
#define GLEN   5
#define ELEN   20
#define H      12
#define HD     64
#define TOPK   5

// Output rows: one row = HD floats = 16 float4 = 256 bytes.
#define G_ROWS     (LG*2*B*H*GLEN)              // 92,160
#define E_ROWS     (LE*2*B*H*(TOPK*ELEN))       // 1,843,200
#define G_PAIRS    (G_ROWS*8)                   // 737,280

#define THREADS    256
#define G_BLOCKS   (G_PAIRS/THREADS)            // 2,880 (exact)
#define E_TILE_BLOCKS (12*H*ELEN)               // 12*12*20 = 2,880
#define TOTAL_BLOCKS (G_BLOCKS + E_TILE_BLOCKS) // 5,760

#define NROWS_BK   (B*TOPK)                     // 640 (b,k) rows per tile

// scratch for selected indices (no cudaMalloc allowed)
__device__ int d_idx[B * TOPK];

// ---------------------------------------------------------------------------
// Kernel 1: cosine-sim + top-5 selection (proven variant).
// qn dropped (positive per-row constant => ranking invariant); tie-break =
// lowest index (jax.lax.top_k order).
// ---------------------------------------------------------------------------
__global__ __launch_bounds__(512) void select_topk_kernel(
        const float4* __restrict__ query4,
        const float4* __restrict__ keys4) {
    const int b    = blockIdx.x;
    const int t    = threadIdx.x;
    const int warp = t >> 5;
    const int lane = t & 31;

    __shared__ float sims[POOL];

    const float4* qr = query4 + (size_t)b * (D / 4);
    float4 fq[6];
    #pragma unroll
    for (int j = 0; j < 6; j++) fq[j] = __ldg(&qr[lane + 32 * j]);

    for (int p = warp; p < POOL; p += 16) {
        const float4* kr = keys4 + (size_t)p * (D / 4);
        float dot = 0.f, kk = 0.f;
        #pragma unroll
        for (int j = 0; j < 6; j++) {
            float4 kv = __ldg(&kr[lane + 32 * j]);
            dot = fmaf(fq[j].x, kv.x, dot);
            dot = fmaf(fq[j].y, kv.y, dot);
            dot = fmaf(fq[j].z, kv.z, dot);
            dot = fmaf(fq[j].w, kv.w, dot);
            kk  = fmaf(kv.x, kv.x, kk);
            kk  = fmaf(kv.y, kv.y, kk);
            kk  = fmaf(kv.z, kv.z, kk);
            kk  = fmaf(kv.w, kv.w, kk);
        }
        #pragma unroll
        for (int o = 16; o > 0; o >>= 1) {
            dot += __shfl_xor_sync(0xFFFFFFFFu, dot, o);
            kk  += __shfl_xor_sync(0xFFFFFFFFu, kk,  o);
        }
        if (lane == 0) {
            float kn = fmaxf(sqrtf(kk), 1e-12f);
            sims[p] = dot / kn;
        }
    }
    __syncthreads();

    if (warp == 0) {
        #pragma unroll
        for (int k = 0; k < TOPK; k++) {
            float best = -3.0e38f;
            int   bi   = POOL;
            #pragma unroll
            for (int j = 0; j < 4; j++) {
                int p = lane + 32 * j;
                if (p < POOL) {
                    float v = sims[p];
                    if (v > best) { best = v; bi = p; }
                }
            }
            #pragma unroll
            for (int o = 16; o > 0; o >>= 1) {
                float ov = __shfl_xor_sync(0xFFFFFFFFu, best, o);
                int   oi = __shfl_xor_sync(0xFFFFFFFFu, bi,   o);
                if (ov > best || (ov == best && oi < bi)) { best = ov; bi = oi; }
            }
            if (lane == 0) {
                d_idx[b * TOPK + k] = bi;
                sims[bi] = -3.0e38f;
            }
            __syncwarp();
        }
    }
}

// ---------------------------------------------------------------------------
// Kernel 2: writer with SMEM-staged e-gather.
//  blocks [0, 2880):  g region, R4 pattern (no smem use).
//  blocks [2880, 5760): e tiles. One block per (ld,h,e): loads the 100
//    candidate pool rows (25.6KB, read ONCE from L2 instead of 6.7x) plus
//    all 640 indices into smem, then writes 640 output rows from smem.
//    Cuts LTS read traffic 495MB -> 74MB; stores keep R4's perfect
//    4x128B-line coalescing (8 threads x 16B cover each 128B half-row).
// ---------------------------------------------------------------------------
__global__ __launch_bounds__(THREADS) void write_out_kernel(
        const float4* __restrict__ g4,
        const float4* __restrict__ pool4,
        float4* __restrict__ out4) {
    __shared__ float4 s_pool[POOL][16];   // 25.6 KB
    __shared__ int    s_idx[NROWS_BK];    // 2.56 KB

    const int blk = blockIdx.x;
    const int tid = threadIdx.x;

    if (blk < G_BLOCKS) {
        // ===== g region: out[ld,b,h,gl,:] = g_prompt[ld,gl,h,:] =====
        int gid = blk * THREADS + tid;         // < G_PAIRS exact
        const int c4h = gid & 7;
        const int row = gid >> 3;
        int v  = row;
        int gl = v % GLEN; v /= GLEN;
        int h  = v % H;    v /= H;
        v >>= 7;                               // drop b
        int ld = v;                            // 0..11
        const float4* src = &g4[(((ld * GLEN + gl) * H + h) << 4) + c4h];
        float4 v0 = __ldg(src);
        float4 v1 = __ldg(src + 8);
        float4* dst = out4 + ((long long)row << 4) + c4h;
        __stcs(dst,     v0);
        __stcs(dst + 8, v1);
        return;
    }

    // ===== e tile: (ld, h, e) =====
    int eb = blk - G_BLOCKS;                   // 0..2879
    const int e  = eb % ELEN;  eb /= ELEN;
    const int h  = eb % H;     eb /= H;
    const int ld = eb;                          // 0..11

    // load the 100 candidate pool rows for this (ld,e,h): 1600 float4
    // pool float4 layout: [POOL, 12, ELEN, H, 16]
    {
        const int base_off = (ld * ELEN + e) * H + h;   // per-p offset term
        for (int i = tid; i < POOL * 16; i += THREADS) {
            int p = i >> 4;
            int c = i & 15;
            s_pool[p][c] = __ldg(&pool4[(((p * 12 * ELEN * H) + (base_off << 0)) << 4)
                                        + (p ? 0 : 0) /*noop*/ + c]
                                 + ((long long)0));
        }
    }
    // NOTE: the expression above must be exact; rewrite cleanly:
    // (recomputed below — the loop above already wrote correct values only if
    //  the index matched; do it properly instead)
    __syncthreads();  // harmless ordering point before the authoritative load
    {
        for (int i = tid; i < POOL * 16; i += THREADS) {
            int p = i >> 4;
            int c = i & 15;
            s_pool[p][c] = __ldg(&pool4[((((p * 12 + ld) * ELEN + e) * H + h) << 4) + c]);
        }
        for (int j = tid; j < NROWS_BK; j += THREADS) {
            s_idx[j] = d_idx[j];
        }
    }
    __syncthreads();

    // write 640 rows x 8 half-pairs = 5120 tasks, 20 per thread
    // row = b*TOPK + k ; out row index = G_ROWS + ((ld*B + b)*H + h)*100 + k*ELEN + e
    const long long out_tile_base = (long long)G_ROWS + ((long long)ld * B * H + h) * 100 + e;
    for (int id = tid; id < NROWS_BK * 8; id += THREADS) {
        const int c4h = id & 7;
        const int row = id >> 3;               // b*5 + k
        const int b   = row / TOPK;
        const int k   = row - b * TOPK;
        const int p   = s_idx[row];

        float4 v0 = s_pool[p][c4h];
        float4 v1 = s_pool[p][c4h + 8];

        const long long orow = out_tile_base + (long long)b * (H * 100) + k * ELEN;
        float4* dst = out4 + (orow << 4) + c4h;
        __stcs(dst,     v0);
        __stcs(dst + 8, v1);
    }
}

// ---------------------------------------------------------------------------
extern "C" void kernel_launch(void* const* d_in, const int* in_sizes, int n_in,
                              void* d_out, int out_size) {
    const float* query = (const float*)d_in[0];
    const float* gprm  = (const float*)d_in[1];
    const float* pool  = (const float*)d_in[2];
    const float* keys  = (const float*)d_in[3];
    float* out = (float*)d_out;

    // 1. top-k selection
    select_topk_kernel<<<B, 512>>>((const float4*)query, (const float4*)keys);

    // 2. writer (g blocks + smem-staged e tiles)
    write_out_kernel<<<TOTAL_BLOCKS, THREADS>>>((const float4*)gprm,
                                                (const float4*)pool,
                                                (float4*)out);
}

// round 13
// speedup vs baseline: 1.0274x; 1.0274x over previous
#include <cuda_runtime.h>
#include <cstdint>

// ---------------- problem constants ----------------
#define B      128
#define D      768
#define POOL   100
#define LG     6
#define LE     6
#define GLEN   5
#define ELEN   20
#define H      12
#define HD     64
#define TOPK   5

// Output rows: one row = HD floats = 16 float4 = 256 bytes.
#define G_ROWS     (LG*2*B*H*GLEN)              // 92,160
#define E_ROWS     (LE*2*B*H*(TOPK*ELEN))       // 1,843,200
#define G_PAIRS    (G_ROWS*8)                   // 737,280

#define THREADS    256
#define G_BLOCKS   (G_PAIRS/THREADS)            // 2,880 (exact)
#define E_TILE_BLOCKS (12*H*ELEN)               // 2,880
#define TOTAL_BLOCKS (G_BLOCKS + E_TILE_BLOCKS) // 5,760

#define NROWS_BK   (B*TOPK)                     // 640 (b,k) rows per tile

// scratch for selected indices (no cudaMalloc allowed)
__device__ int d_idx[B * TOPK];

// ---------------------------------------------------------------------------
// Kernel 1 (PDL primary): cosine-sim + top-5 selection (proven variant).
// qn dropped (positive per-row constant => ranking invariant); tie-break =
// lowest index (jax.lax.top_k order). Triggers PDL completion when done.
// ---------------------------------------------------------------------------
__global__ __launch_bounds__(512) void select_topk_kernel(
        const float4* __restrict__ query4,
        const float4* __restrict__ keys4) {
    const int b    = blockIdx.x;
    const int t    = threadIdx.x;
    const int warp = t >> 5;
    const int lane = t & 31;

    __shared__ float sims[POOL];

    const float4* qr = query4 + (size_t)b * (D / 4);
    float4 fq[6];
    #pragma unroll
    for (int j = 0; j < 6; j++) fq[j] = __ldg(&qr[lane + 32 * j]);

    for (int p = warp; p < POOL; p += 16) {
        const float4* kr = keys4 + (size_t)p * (D / 4);
        float dot = 0.f, kk = 0.f;
        #pragma unroll
        for (int j = 0; j < 6; j++) {
            float4 kv = __ldg(&kr[lane + 32 * j]);
            dot = fmaf(fq[j].x, kv.x, dot);
            dot = fmaf(fq[j].y, kv.y, dot);
            dot = fmaf(fq[j].z, kv.z, dot);
            dot = fmaf(fq[j].w, kv.w, dot);
            kk  = fmaf(kv.x, kv.x, kk);
            kk  = fmaf(kv.y, kv.y, kk);
            kk  = fmaf(kv.z, kv.z, kk);
            kk  = fmaf(kv.w, kv.w, kk);
        }
        #pragma unroll
        for (int o = 16; o > 0; o >>= 1) {
            dot += __shfl_xor_sync(0xFFFFFFFFu, dot, o);
            kk  += __shfl_xor_sync(0xFFFFFFFFu, kk,  o);
        }
        if (lane == 0) {
            float kn = fmaxf(sqrtf(kk), 1e-12f);
            sims[p] = dot / kn;
        }
    }
    __syncthreads();

    if (warp == 0) {
        #pragma unroll
        for (int k = 0; k < TOPK; k++) {
            float best = -3.0e38f;
            int   bi   = POOL;
            #pragma unroll
            for (int j = 0; j < 4; j++) {
                int p = lane + 32 * j;
                if (p < POOL) {
                    float v = sims[p];
                    if (v > best) { best = v; bi = p; }
                }
            }
            #pragma unroll
            for (int o = 16; o > 0; o >>= 1) {
                float ov = __shfl_xor_sync(0xFFFFFFFFu, best, o);
                int   oi = __shfl_xor_sync(0xFFFFFFFFu, bi,   o);
                if (ov > best || (ov == best && oi < bi)) { best = ov; bi = oi; }
            }
            if (lane == 0) {
                d_idx[b * TOPK + k] = bi;
                sims[bi] = -3.0e38f;
            }
            __syncwarp();
        }
    }
    __syncthreads();
    cudaTriggerProgrammaticLaunchCompletion();
}

// ---------------------------------------------------------------------------
// Kernel 2 (PDL secondary): writer with SMEM-staged e-gather (clean).
//  blocks [0, 2880):    g region, R4 pattern (no dependency, overlaps primary)
//  blocks [2880, 5760): e tiles, one per (ld,h,e). Loads the 100 candidate
//    pool rows (25.6KB) ONCE + 640 indices into smem, then writes 640 rows.
//    s_pool padded to 17 float4/row -> per-row bank offset of 4 -> the 4
//    rows a warp touches in the store phase hit different banks
//    (conflict-free; smem read BW ~38 B/cyc/SM << 128 cap).
//    L2 read traffic: 495MB -> 74MB.
// ---------------------------------------------------------------------------
__global__ __launch_bounds__(THREADS) void write_out_kernel(
        const float4* __restrict__ g4,
        const float4* __restrict__ pool4,
        float4* __restrict__ out4) {
    __shared__ float4 s_pool[POOL][17];   // padded: 27.2 KB
    __shared__ int    s_idx[NROWS_BK];    // 2.56 KB

    const int blk = blockIdx.x;
    const int tid = threadIdx.x;

    if (blk < G_BLOCKS) {
        // ===== g region: out[ld,b,h,gl,:] = g_prompt[ld,gl,h,:] =====
        int gid = blk * THREADS + tid;         // < G_PAIRS exact
        const int c4h = gid & 7;
        const int row = gid >> 3;
        int v  = row;
        int gl = v % GLEN; v /= GLEN;
        int h  = v % H;    v /= H;
        v >>= 7;                               // drop b
        int ld = v;                            // 0..11
        const float4* src = &g4[(((ld * GLEN + gl) * H + h) << 4) + c4h];
        float4 v0 = __ldg(src);
        float4 v1 = __ldg(src + 8);
        float4* dst = out4 + ((long long)row << 4) + c4h;
        __stcs(dst,     v0);
        __stcs(dst + 8, v1);
        return;
    }

    // ===== e tile: (ld, h, e) =====
    int eb = blk - G_BLOCKS;                   // 0..2879
    const int e  = eb % ELEN;  eb /= ELEN;
    const int h  = eb % H;     eb /= H;
    const int ld = eb;                          // 0..11

    // wait for primary grid's d_idx (HW dependency; satisfied before any
    // secondary block runs under PDL semantics)
    cudaGridDependencySynchronize();

    // load the 100 candidate pool rows for this (ld,e,h): 1600 float4
    // pool float4 layout: [POOL, 12, ELEN, H, 16]
    for (int i = tid; i < POOL * 16; i += THREADS) {
        int p = i >> 4;
        int c = i & 15;
        s_pool[p][c] = __ldg(&pool4[((((p * 12 + ld) * ELEN + e) * H + h) << 4) + c]);
    }
    for (int j = tid; j < NROWS_BK; j += THREADS) {
        s_idx[j] = d_idx[j];
    }
    __syncthreads();

    // store phase: 640 rows x 8 half-pairs = 5120 tasks, 20 per thread.
    // c4h is constant per thread (stride 256 ≡ 0 mod 8); row strides by 32.
    // out row = G_ROWS + ((ld*B + b)*H + h)*100 + k*ELEN + e
    const long long out_tile_base =
        (long long)G_ROWS + ((long long)ld * B * H + h) * 100 + e;
    const int c4h  = tid & 7;
    int       row  = tid >> 3;                 // starting (b*5+k) row
    #pragma unroll 4
    for (int it = 0; it < (NROWS_BK * 8) / THREADS; it++, row += 32) {
        const int b = row / TOPK;
        const int k = row - b * TOPK;
        const int p = s_idx[row];

        float4 v0 = s_pool[p][c4h];
        float4 v1 = s_pool[p][c4h + 8];

        const long long orow = out_tile_base + (long long)b * (H * 100) + k * ELEN;
        float4* dst = out4 + (orow << 4) + c4h;
        __stcs(dst,     v0);
        __stcs(dst + 8, v1);
    }
}

// ---------------------------------------------------------------------------
extern "C" void kernel_launch(void* const* d_in, const int* in_sizes, int n_in,
                              void* d_out, int out_size) {
    const float* query = (const float*)d_in[0];
    const float* gprm  = (const float*)d_in[1];
    const float* pool  = (const float*)d_in[2];
    const float* keys  = (const float*)d_in[3];
    float* out = (float*)d_out;

    // 1. top-k selection (PDL primary)
    select_topk_kernel<<<B, 512>>>((const float4*)query, (const float4*)keys);

    // 2. writer (PDL secondary): g blocks overlap selection; e tiles gated
    //    by the HW grid dependency.
    {
        cudaLaunchConfig_t cfg = {};
        cfg.gridDim  = dim3(TOTAL_BLOCKS);
        cfg.blockDim = dim3(THREADS);
        cudaLaunchAttribute attr[1];
        attr[0].id = cudaLaunchAttributeProgrammaticStreamSerialization;
        attr[0].val.programmaticStreamSerializationAllowed = 1;
        cfg.attrs    = attr;
        cfg.numAttrs = 1;
        cudaLaunchKernelEx(&cfg, write_out_kernel,
                           (const float4*)gprm, (const float4*)pool,
                           (float4*)out);
    }
}